// round 16
// baseline (speedup 1.0000x reference)
#include <cuda_runtime.h>
#include <cuda_fp16.h>
#include <stdint.h>

#define NN 50000
#define EE 800000
#define DIMK 64
#define BN_EPS 1e-5f
#define L2_EPS 1e-12f
#define NB 148
#define BT 1024

// ---- scratch (device globals; no allocation allowed) ----
__device__ __align__(16) float  g_h[NN * DIMK];    // h = x @ W (fp32, self-loop read)
__device__ __align__(16) __half g_hh[NN * DIMK];   // h in fp16 (gather side)
__device__ __align__(16) float  g_acc[NN * DIMK];  // aggregated rows
__device__ int   g_degi[NN];                       // reset inside build each launch
__device__ int   g_rank[EE];                       // within-dst rank per edge
__device__ int   g_rowptr[NN + 1];
__device__ int   g_blkv[NB];                       // scan block totals
__device__ int   g_blkf[NB];                       // publish flags
__device__ int   g_csri[EE];                       // src indices grouped by dst
__device__ float g_dinv[NN];
__device__ float g_sum[DIMK];
__device__ float g_sumsq[DIMK];
__device__ unsigned g_barc;                        // monotonic grid-barrier counter

// Software grid barrier: monotonic counter, self-resetting across replays.
__device__ __forceinline__ void grid_bar() {
    __syncthreads();
    __threadfence();
    if (threadIdx.x == 0) {
        unsigned old = atomicAdd(&g_barc, 1u);
        unsigned target = (old / (unsigned)NB + 1u) * (unsigned)NB;
        while (*(volatile unsigned*)&g_barc < target) { }
    }
    __syncthreads();
}

// ---- 1) persistent build: probe + deg/rank -> bar -> scan -> bar -> fill ----
__global__ void __launch_bounds__(BT, 1) k_build(const void* __restrict__ ei, int n, int E) {
    int tid = threadIdx.x, b = blockIdx.x;
    const int T = NB * BT;
    int gt = b * BT + tid;

    // Phase A: dtype probe (each block; L2 hits) + block 0 zeroes stats; all zero own flag.
    const unsigned* e32 = (const unsigned*)ei;
    unsigned pacc = 0;
    for (int j = tid; j < 2048; j += BT) pacc |= e32[2 * j + 1];
    __shared__ unsigned shp[32];
    // warp-reduce then cross-warp
    #pragma unroll
    for (int o = 16; o > 0; o >>= 1) pacc |= __shfl_xor_sync(0xffffffffu, pacc, o);
    if ((tid & 31) == 0) shp[tid >> 5] = pacc;
    __syncthreads();
    if (tid < 32) {
        unsigned v = shp[tid];
        #pragma unroll
        for (int o = 16; o > 0; o >>= 1) v |= __shfl_xor_sync(0xffffffffu, v, o);
        if (tid == 0) shp[0] = v;
    }
    __syncthreads();
    const int is32 = (shp[0] != 0);
    if (tid == 0) g_blkf[b] = 0;
    if (b == 0 && tid < DIMK) { g_sum[tid] = 0.f; g_sumsq[tid] = 0.f; }

    // Phase B: degree + rank capture (grid-stride over edge pairs).
    const int ehalf = (E + 1) / 2;
    for (int t2 = gt; t2 < ehalf; t2 += T) {
        int e = t2 * 2;
        int d0, d1 = -1;
        if (is32) {
            const int* p = (const int*)ei;
            if (e + 1 < E) { int2 v = *(const int2*)(p + E + e); d0 = v.x; d1 = v.y; }
            else d0 = p[E + e];
        } else {
            const long long* p = (const long long*)ei;
            if (e + 1 < E) { longlong2 v = *(const longlong2*)(p + E + e); d0 = (int)v.x; d1 = (int)v.y; }
            else d0 = (int)p[E + e];
        }
        if (d1 >= 0) {
            int r0, r1;
            if (d0 == d1) { r0 = atomicAdd(&g_degi[d0], 2); r1 = r0 + 1; }
            else { r0 = atomicAdd(&g_degi[d0], 1); r1 = atomicAdd(&g_degi[d1], 1); }
            *(int2*)&g_rank[e] = make_int2(r0, r1);
        } else {
            g_rank[e] = atomicAdd(&g_degi[d0], 1);
        }
    }
    grid_bar();

    // Phase C: scan. Block b owns nodes [b*chunk, b*chunk+chunk).
    const int chunk = (n + NB - 1) / NB;       // 338
    {
        __shared__ int sh[BT];
        __shared__ int pre[NB];
        __shared__ int offs;
        int i = b * chunk + tid;
        int deg = (tid < chunk && i < n) ? g_degi[i] : 0;
        sh[tid] = deg;
        __syncthreads();
        for (int off = 1; off < BT; off <<= 1) {
            int u = (tid >= off) ? sh[tid - off] : 0;
            __syncthreads();
            sh[tid] += u;
            __syncthreads();
        }
        int lexcl = sh[tid] - deg;
        if (tid == BT - 1) {
            g_blkv[b] = sh[tid];
            __threadfence();
            *(volatile int*)&g_blkf[b] = 1;
        }
        if (tid < NB) pre[tid] = 0;
        __syncthreads();
        if (tid < b) {
            while (*(volatile int*)&g_blkf[tid] == 0) { }
            pre[tid] = g_blkv[tid];
        }
        __syncthreads();
        if (tid == 0) {
            int s = 0;
            for (int j = 0; j < b; j++) s += pre[j];
            offs = s;
        }
        __syncthreads();
        if (tid < chunk && i < n) {
            g_rowptr[i] = lexcl + offs;
            g_dinv[i]   = rsqrtf((float)(1 + deg));
            g_degi[i]   = 0;                        // ready for next replay
        }
        if (b == 0 && tid == 0) g_rowptr[n] = E;
    }
    grid_bar();

    // Phase D: fill CSR (atomic-free, rank-based).
    for (int t2 = gt; t2 < ehalf; t2 += T) {
        int e = t2 * 2;
        int s0, d0, s1 = -1, d1 = -1;
        if (is32) {
            const int* p = (const int*)ei;
            if (e + 1 < E) {
                int2 sv = *(const int2*)(p + e);
                int2 dv = *(const int2*)(p + E + e);
                s0 = sv.x; s1 = sv.y; d0 = dv.x; d1 = dv.y;
            } else { s0 = p[e]; d0 = p[E + e]; }
        } else {
            const long long* p = (const long long*)ei;
            if (e + 1 < E) {
                longlong2 sv = *(const longlong2*)(p + e);
                longlong2 dv = *(const longlong2*)(p + E + e);
                s0 = (int)sv.x; s1 = (int)sv.y; d0 = (int)dv.x; d1 = (int)dv.y;
            } else { s0 = (int)p[e]; d0 = (int)p[E + e]; }
        }
        if (d1 >= 0) {
            int2 rk = *(const int2*)&g_rank[e];
            g_csri[g_rowptr[d0] + rk.x] = s0;
            g_csri[g_rowptr[d1] + rk.y] = s1;
        } else {
            g_csri[g_rowptr[d0] + g_rank[e]] = s0;
        }
    }
}

// ---- 2) GEMM h = x@W (register-tiled 4x4) -> fp32 g_h + fp16 g_hh (side stream) ----
__global__ void k_gemm(const float* __restrict__ x, const float* __restrict__ W, int n) {
    __shared__ float Wsh[DIMK][68];
    __shared__ float xsh[DIMK][68];
    int tid = threadIdx.x;
    int row0 = blockIdx.x * 64;

    for (int i = tid; i < 1024; i += 256) {
        int r  = i >> 4;
        int c4 = (i & 15) << 2;
        *(float4*)&Wsh[r][c4] = ((const float4*)W)[i];
    }
    for (int i = tid; i < 1024; i += 256) {
        int r  = i >> 4;
        int c4 = (i & 15) << 2;
        int gr = row0 + r;
        float4 v = (gr < n) ? ((const float4*)x)[(size_t)gr * 16 + (i & 15)]
                            : make_float4(0.f, 0.f, 0.f, 0.f);
        *(float4*)&xsh[r][c4] = v;
    }
    __syncthreads();

    int tr = tid >> 4;
    int tc = (tid & 15) << 2;
    float acc[4][4] = {};
    #pragma unroll
    for (int k = 0; k < DIMK; k++) {
        float4 wv = *(const float4*)&Wsh[k][tc];
        float xv[4];
        #pragma unroll
        for (int i = 0; i < 4; i++) xv[i] = xsh[i * 16 + tr][k];
        #pragma unroll
        for (int i = 0; i < 4; i++) {
            acc[i][0] = fmaf(xv[i], wv.x, acc[i][0]);
            acc[i][1] = fmaf(xv[i], wv.y, acc[i][1]);
            acc[i][2] = fmaf(xv[i], wv.z, acc[i][2]);
            acc[i][3] = fmaf(xv[i], wv.w, acc[i][3]);
        }
    }
    #pragma unroll
    for (int i = 0; i < 4; i++) {
        int r = row0 + i * 16 + tr;
        if (r >= n) continue;
        size_t o = (size_t)r * DIMK + tc;
        *(float4*)&g_h[o] = make_float4(acc[i][0], acc[i][1], acc[i][2], acc[i][3]);
        __half2 hlo = __floats2half2_rn(acc[i][0], acc[i][1]);
        __half2 hhi = __floats2half2_rn(acc[i][2], acc[i][3]);
        uint2 hp; hp.x = *(unsigned int*)&hlo; hp.y = *(unsigned int*)&hhi;
        *(uint2*)&g_hh[o] = hp;
    }
}

// ---- 3) aggregate: warp per dst; fp16 edge gather, fp32 accumulate + BN stats ----
__global__ void k_agg(int n) {
    __shared__ float shs[8][DIMK];
    __shared__ float shq[8][DIMK];
    int lane = threadIdx.x & 31;
    int w    = threadIdx.x >> 5;             // 0..7
    int dst  = blockIdx.x * 8 + w;
    int c2   = lane * 2;

    float a0 = 0.f, a1 = 0.f;
    if (dst < n) {
        float dv = g_dinv[dst];
        size_t hb = (size_t)dst * DIMK;
        float2 sl = *(const float2*)&g_h[hb + c2];
        a0 = sl.x * (dv * dv);
        a1 = sl.y * (dv * dv);
        int p  = g_rowptr[dst];
        int p1 = g_rowptr[dst + 1];
        for (; p + 3 < p1; p += 4) {
            int s0i = g_csri[p];
            int s1i = g_csri[p + 1];
            int s2i = g_csri[p + 2];
            int s3i = g_csri[p + 3];
            unsigned int v0 = *(const unsigned int*)&g_hh[(size_t)s0i * DIMK + c2];
            unsigned int v1 = *(const unsigned int*)&g_hh[(size_t)s1i * DIMK + c2];
            unsigned int v2 = *(const unsigned int*)&g_hh[(size_t)s2i * DIMK + c2];
            unsigned int v3 = *(const unsigned int*)&g_hh[(size_t)s3i * DIMK + c2];
            float n0 = g_dinv[s0i] * dv;
            float n1 = g_dinv[s1i] * dv;
            float n2 = g_dinv[s2i] * dv;
            float n3 = g_dinv[s3i] * dv;
            float2 f0 = __half22float2(*(const __half2*)&v0);
            float2 f1 = __half22float2(*(const __half2*)&v1);
            float2 f2 = __half22float2(*(const __half2*)&v2);
            float2 f3 = __half22float2(*(const __half2*)&v3);
            a0 = fmaf(n0, f0.x, a0); a1 = fmaf(n0, f0.y, a1);
            a0 = fmaf(n1, f1.x, a0); a1 = fmaf(n1, f1.y, a1);
            a0 = fmaf(n2, f2.x, a0); a1 = fmaf(n2, f2.y, a1);
            a0 = fmaf(n3, f3.x, a0); a1 = fmaf(n3, f3.y, a1);
        }
        for (; p < p1; p++) {
            int s0i = g_csri[p];
            float n0 = g_dinv[s0i] * dv;
            unsigned int v0 = *(const unsigned int*)&g_hh[(size_t)s0i * DIMK + c2];
            float2 f0 = __half22float2(*(const __half2*)&v0);
            a0 = fmaf(n0, f0.x, a0); a1 = fmaf(n0, f0.y, a1);
        }
        *(float2*)&g_acc[hb + c2] = make_float2(a0, a1);
    }

    shs[w][c2] = a0; shs[w][c2 + 1] = a1;
    shq[w][c2] = a0 * a0; shq[w][c2 + 1] = a1 * a1;
    __syncthreads();
    if (threadIdx.x < DIMK) {
        float ts = 0.f, tq = 0.f;
        #pragma unroll
        for (int i = 0; i < 8; i++) { ts += shs[i][threadIdx.x]; tq += shq[i][threadIdx.x]; }
        atomicAdd(&g_sum[threadIdx.x], ts);
        atomicAdd(&g_sumsq[threadIdx.x], tq);
    }
}

// ---- 4) finalize (vectorized): BN -> ReLU -> L2 normalize -> out ----
__global__ void k_final(const float* __restrict__ gamma, const float* __restrict__ beta,
                        float* __restrict__ out, int n) {
    int warp = (blockIdx.x * blockDim.x + threadIdx.x) >> 5;
    int lane = threadIdx.x & 31;
    if (warp >= n) return;
    const float invN = 1.0f / (float)n;
    int c2 = lane * 2;

    float2 sm = *(const float2*)&g_sum[c2];
    float2 sq = *(const float2*)&g_sumsq[c2];
    float2 gm = *(const float2*)&gamma[c2];
    float2 bt = *(const float2*)&beta[c2];
    float m0 = sm.x * invN, m1 = sm.y * invN;
    float v0 = sq.x * invN - m0 * m0;
    float v1 = sq.y * invN - m1 * m1;
    float sc0 = rsqrtf(v0 + BN_EPS) * gm.x;
    float sc1 = rsqrtf(v1 + BN_EPS) * gm.y;

    size_t base = (size_t)warp * DIMK;
    float2 a = *(const float2*)&g_acc[base + c2];
    float y0 = fmaf(a.x - m0, sc0, bt.x);
    float y1 = fmaf(a.y - m1, sc1, bt.y);
    y0 = fmaxf(y0, 0.0f);
    y1 = fmaxf(y1, 0.0f);

    float ss = y0 * y0 + y1 * y1;
    #pragma unroll
    for (int o = 16; o > 0; o >>= 1)
        ss += __shfl_xor_sync(0xffffffffu, ss, o);
    float inv = 1.0f / fmaxf(sqrtf(ss), L2_EPS);
    *(float2*)&out[base + c2] = make_float2(y0 * inv, y1 * inv);
}

extern "C" void kernel_launch(void* const* d_in, const int* in_sizes, int n_in,
                              void* d_out, int out_size) {
    const float* x     = (const float*)d_in[0];
    const void*  ei    = d_in[1];                 // int32 or int64, probed on device
    const float* W     = (const float*)d_in[2];
    // const float* b  = (const float*)d_in[3];   // cancels exactly in BN
    const float* gamma = (const float*)d_in[4];
    const float* beta  = (const float*)d_in[5];
    float* out = (float*)d_out;

    int n = in_sizes[0] / DIMK;       // 50000
    int E = in_sizes[1] / 2;          // 800000

    static int s_inited = 0;
    static cudaStream_t s_side;
    static cudaEvent_t  s_fork, s_join;
    if (!s_inited) {
        cudaStreamCreateWithFlags(&s_side, cudaStreamNonBlocking);
        cudaEventCreateWithFlags(&s_fork, cudaEventDisableTiming);
        cudaEventCreateWithFlags(&s_join, cudaEventDisableTiming);
        s_inited = 1;
    }

    // Main stream: persistent CSR build FIRST (1 block/SM placement priority)...
    cudaEventRecord(s_fork, 0);
    k_build<<<NB, BT>>>(ei, n, E);

    // ...then gemm on the side stream fills the remaining SM capacity.
    cudaStreamWaitEvent(s_side, s_fork, 0);
    k_gemm<<<(n + 63) / 64, 256, 0, s_side>>>(x, W, n);
    cudaEventRecord(s_join, s_side);

    // Join, then aggregate + finalize.
    cudaStreamWaitEvent(0, s_join, 0);
    k_agg  <<<(n + 7) / 8, 256>>>(n);
    k_final<<<(n + 7) / 8, 256>>>(gamma, beta, out, n);
}

// round 17
// speedup vs baseline: 1.0652x; 1.0652x over previous
#include <cuda_runtime.h>
#include <cuda_fp16.h>
#include <stdint.h>

#define NN 50000
#define EE 800000
#define DIMK 64
#define BN_EPS 1e-5f
#define L2_EPS 1e-12f
#define SCAN_B 1024
#define NBLK_MAX 64

// ---- scratch (device globals; no allocation allowed) ----
__device__ __align__(16) __half g_hh[NN * DIMK];   // h = x @ W in fp16
__device__ __align__(16) float  g_acc[NN * DIMK];  // aggregated rows
__device__ int   g_degi[NN];                       // zeroed by scan each launch
__device__ int   g_rank[EE];                       // within-dst rank per edge
__device__ int   g_rowptr[NN + 1];
__device__ int   g_blkv[NBLK_MAX];                 // scan block totals
__device__ int   g_blkf[NBLK_MAX];                 // publish flags (zeroed by k_deg)
__device__ int   g_csri[EE];                       // src indices grouped by dst
__device__ float g_dinv[NN];
__device__ float g_sum[DIMK];
__device__ float g_sumsq[DIMK];
__device__ int   g_is32;                           // 1 if edge_index is int32

// ---- 1) degree + rank capture (+inline dtype probe, +zero flags/stats) ----
__global__ void k_deg(const void* __restrict__ ei, int E) {
    // self-probe: every block reads the same 2048 odd words (L2 hits)
    const unsigned* e32 = (const unsigned*)ei;
    unsigned acc = 0;
    for (int j = threadIdx.x; j < 2048; j += blockDim.x) acc |= e32[2 * j + 1];
    __shared__ unsigned shp[256];
    shp[threadIdx.x] = acc;
    __syncthreads();
    for (int s = 128; s > 0; s >>= 1) {
        if (threadIdx.x < s) shp[threadIdx.x] |= shp[threadIdx.x + s];
        __syncthreads();
    }
    int is32 = (shp[0] != 0);
    if (blockIdx.x == 0) {
        if (threadIdx.x == 0) g_is32 = is32;
        if (threadIdx.x < DIMK) { g_sum[threadIdx.x] = 0.f; g_sumsq[threadIdx.x] = 0.f; }
        if (threadIdx.x < NBLK_MAX) g_blkf[threadIdx.x] = 0;
    }

    int t = blockIdx.x * blockDim.x + threadIdx.x;
    int e = t * 2;
    if (e >= E) return;
    int d0, d1 = -1;
    if (is32) {
        const int* p = (const int*)ei;
        if (e + 1 < E) { int2 v = *(const int2*)(p + E + e); d0 = v.x; d1 = v.y; }
        else d0 = p[E + e];
    } else {
        const long long* p = (const long long*)ei;
        if (e + 1 < E) { longlong2 v = *(const longlong2*)(p + E + e); d0 = (int)v.x; d1 = (int)v.y; }
        else d0 = (int)p[E + e];
    }
    if (d1 >= 0) {
        int r0, r1;
        if (d0 == d1) {               // same dst: one atomic for both
            r0 = atomicAdd(&g_degi[d0], 2);
            r1 = r0 + 1;
        } else {
            r0 = atomicAdd(&g_degi[d0], 1);
            r1 = atomicAdd(&g_degi[d1], 1);
        }
        *(int2*)&g_rank[e] = make_int2(r0, r1);
    } else {
        g_rank[e] = atomicAdd(&g_degi[d0], 1);
    }
}

// ---- 2) fused scan (decoupled lookback): rowptr + dinv + degi reset ----
__global__ void k_scan(int n, int E) {
    __shared__ int sh[SCAN_B];
    __shared__ int pre[NBLK_MAX];
    int t = threadIdx.x, b = blockIdx.x;
    int i = b * SCAN_B + t;
    int deg = (i < n) ? g_degi[i] : 0;
    sh[t] = deg;
    __syncthreads();
    for (int off = 1; off < SCAN_B; off <<= 1) {
        int u = (t >= off) ? sh[t - off] : 0;
        __syncthreads();
        sh[t] += u;
        __syncthreads();
    }
    int lexcl = sh[t] - deg;                    // local exclusive
    if (t == SCAN_B - 1) {
        g_blkv[b] = sh[t];
        __threadfence();
        *(volatile int*)&g_blkf[b] = 1;         // publish
    }
    if (t < NBLK_MAX) pre[t] = 0;
    __syncthreads();
    if (t < b) {
        while (*(volatile int*)&g_blkf[t] == 0) { }
        pre[t] = g_blkv[t];
    }
    __syncthreads();
    __shared__ int offs;
    if (t == 0) {
        int s = 0;
        for (int j = 0; j < b; j++) s += pre[j];
        offs = s;
    }
    __syncthreads();
    if (i < n) {
        int rp = lexcl + offs;
        g_rowptr[i] = rp;
        g_dinv[i]   = rsqrtf((float)(1 + deg));
        g_degi[i]   = 0;                        // ready for next replay
    }
    if (i == 0) g_rowptr[n] = E;
}

// ---- 3) GEMM h = x@W (register-tiled 4x4) -> fp16 g_hh (side stream) ----
__global__ void k_gemm(const float* __restrict__ x, const float* __restrict__ W, int n) {
    __shared__ float Wsh[DIMK][68];
    __shared__ float xsh[DIMK][68];
    int tid = threadIdx.x;
    int row0 = blockIdx.x * 64;

    for (int i = tid; i < 1024; i += 256) {
        int r  = i >> 4;
        int c4 = (i & 15) << 2;
        *(float4*)&Wsh[r][c4] = ((const float4*)W)[i];
    }
    for (int i = tid; i < 1024; i += 256) {
        int r  = i >> 4;
        int c4 = (i & 15) << 2;
        int gr = row0 + r;
        float4 v = (gr < n) ? ((const float4*)x)[(size_t)gr * 16 + (i & 15)]
                            : make_float4(0.f, 0.f, 0.f, 0.f);
        *(float4*)&xsh[r][c4] = v;
    }
    __syncthreads();

    int tr = tid >> 4;
    int tc = (tid & 15) << 2;
    float acc[4][4] = {};
    #pragma unroll
    for (int k = 0; k < DIMK; k++) {
        float4 wv = *(const float4*)&Wsh[k][tc];
        float xv[4];
        #pragma unroll
        for (int i = 0; i < 4; i++) xv[i] = xsh[i * 16 + tr][k];
        #pragma unroll
        for (int i = 0; i < 4; i++) {
            acc[i][0] = fmaf(xv[i], wv.x, acc[i][0]);
            acc[i][1] = fmaf(xv[i], wv.y, acc[i][1]);
            acc[i][2] = fmaf(xv[i], wv.z, acc[i][2]);
            acc[i][3] = fmaf(xv[i], wv.w, acc[i][3]);
        }
    }
    #pragma unroll
    for (int i = 0; i < 4; i++) {
        int r = row0 + i * 16 + tr;
        if (r >= n) continue;
        size_t o = (size_t)r * DIMK + tc;
        __half2 hlo = __floats2half2_rn(acc[i][0], acc[i][1]);
        __half2 hhi = __floats2half2_rn(acc[i][2], acc[i][3]);
        uint2 hp; hp.x = *(unsigned int*)&hlo; hp.y = *(unsigned int*)&hhi;
        *(uint2*)&g_hh[o] = hp;
    }
}

// ---- 4) fill CSR: atomic-free — pos = rowptr[dst] + rank[e] ----
__global__ void k_fill(const void* __restrict__ ei, int E) {
    int t = blockIdx.x * blockDim.x + threadIdx.x;
    int e = t * 2;
    if (e >= E) return;
    int s0, d0, s1 = -1, d1 = -1;
    if (g_is32) {
        const int* p = (const int*)ei;
        if (e + 1 < E) {
            int2 sv = *(const int2*)(p + e);
            int2 dv = *(const int2*)(p + E + e);
            s0 = sv.x; s1 = sv.y; d0 = dv.x; d1 = dv.y;
        } else { s0 = p[e]; d0 = p[E + e]; }
    } else {
        const long long* p = (const long long*)ei;
        if (e + 1 < E) {
            longlong2 sv = *(const longlong2*)(p + e);
            longlong2 dv = *(const longlong2*)(p + E + e);
            s0 = (int)sv.x; s1 = (int)sv.y; d0 = (int)dv.x; d1 = (int)dv.y;
        } else { s0 = (int)p[e]; d0 = (int)p[E + e]; }
    }
    if (d1 >= 0) {
        int2 rk = *(const int2*)&g_rank[e];
        g_csri[g_rowptr[d0] + rk.x] = s0;
        g_csri[g_rowptr[d1] + rk.y] = s1;
    } else {
        g_csri[g_rowptr[d0] + g_rank[e]] = s0;
    }
}

// ---- 5) aggregate: warp per dst; fp16 gather (incl. self-loop) + BN stats ----
__global__ void k_agg(int n) {
    __shared__ float shs[8][DIMK];
    __shared__ float shq[8][DIMK];
    int lane = threadIdx.x & 31;
    int w    = threadIdx.x >> 5;             // 0..7
    int dst  = blockIdx.x * 8 + w;
    int c2   = lane * 2;

    float a0 = 0.f, a1 = 0.f;
    if (dst < n) {
        float dv = g_dinv[dst];
        size_t hb = (size_t)dst * DIMK;
        unsigned int sv = *(const unsigned int*)&g_hh[hb + c2];
        float2 sl = __half22float2(*(const __half2*)&sv);
        a0 = sl.x * (dv * dv);
        a1 = sl.y * (dv * dv);
        int p  = g_rowptr[dst];
        int p1 = g_rowptr[dst + 1];
        for (; p + 3 < p1; p += 4) {
            int s0i = g_csri[p];
            int s1i = g_csri[p + 1];
            int s2i = g_csri[p + 2];
            int s3i = g_csri[p + 3];
            unsigned int v0 = *(const unsigned int*)&g_hh[(size_t)s0i * DIMK + c2];
            unsigned int v1 = *(const unsigned int*)&g_hh[(size_t)s1i * DIMK + c2];
            unsigned int v2 = *(const unsigned int*)&g_hh[(size_t)s2i * DIMK + c2];
            unsigned int v3 = *(const unsigned int*)&g_hh[(size_t)s3i * DIMK + c2];
            float n0 = g_dinv[s0i] * dv;
            float n1 = g_dinv[s1i] * dv;
            float n2 = g_dinv[s2i] * dv;
            float n3 = g_dinv[s3i] * dv;
            float2 f0 = __half22float2(*(const __half2*)&v0);
            float2 f1 = __half22float2(*(const __half2*)&v1);
            float2 f2 = __half22float2(*(const __half2*)&v2);
            float2 f3 = __half22float2(*(const __half2*)&v3);
            a0 = fmaf(n0, f0.x, a0); a1 = fmaf(n0, f0.y, a1);
            a0 = fmaf(n1, f1.x, a0); a1 = fmaf(n1, f1.y, a1);
            a0 = fmaf(n2, f2.x, a0); a1 = fmaf(n2, f2.y, a1);
            a0 = fmaf(n3, f3.x, a0); a1 = fmaf(n3, f3.y, a1);
        }
        for (; p < p1; p++) {
            int s0i = g_csri[p];
            float n0 = g_dinv[s0i] * dv;
            unsigned int v0 = *(const unsigned int*)&g_hh[(size_t)s0i * DIMK + c2];
            float2 f0 = __half22float2(*(const __half2*)&v0);
            a0 = fmaf(n0, f0.x, a0); a1 = fmaf(n0, f0.y, a1);
        }
        *(float2*)&g_acc[hb + c2] = make_float2(a0, a1);
    }

    shs[w][c2] = a0; shs[w][c2 + 1] = a1;
    shq[w][c2] = a0 * a0; shq[w][c2 + 1] = a1 * a1;
    __syncthreads();
    if (threadIdx.x < DIMK) {
        float ts = 0.f, tq = 0.f;
        #pragma unroll
        for (int i = 0; i < 8; i++) { ts += shs[i][threadIdx.x]; tq += shq[i][threadIdx.x]; }
        atomicAdd(&g_sum[threadIdx.x], ts);
        atomicAdd(&g_sumsq[threadIdx.x], tq);
    }
}

// ---- 6) finalize: half-warp (16 lanes) per row, float4 per lane ----
__global__ void k_final(const float* __restrict__ gamma, const float* __restrict__ beta,
                        float* __restrict__ out, int n) {
    int gthread = blockIdx.x * blockDim.x + threadIdx.x;
    int row  = gthread >> 4;                  // 16 lanes per row
    int l16  = threadIdx.x & 15;
    if (row >= n) return;
    const float invN = 1.0f / (float)n;
    int c4 = l16 * 4;

    float4 sm = *(const float4*)&g_sum[c4];
    float4 sq = *(const float4*)&g_sumsq[c4];
    float4 gm = *(const float4*)&gamma[c4];
    float4 bt = *(const float4*)&beta[c4];
    float m0 = sm.x * invN, m1 = sm.y * invN, m2 = sm.z * invN, m3 = sm.w * invN;
    float sc0 = rsqrtf(sq.x * invN - m0 * m0 + BN_EPS) * gm.x;
    float sc1 = rsqrtf(sq.y * invN - m1 * m1 + BN_EPS) * gm.y;
    float sc2 = rsqrtf(sq.z * invN - m2 * m2 + BN_EPS) * gm.z;
    float sc3 = rsqrtf(sq.w * invN - m3 * m3 + BN_EPS) * gm.w;

    size_t base = (size_t)row * DIMK;
    float4 a = *(const float4*)&g_acc[base + c4];
    float y0 = fmaxf(fmaf(a.x - m0, sc0, bt.x), 0.0f);
    float y1 = fmaxf(fmaf(a.y - m1, sc1, bt.y), 0.0f);
    float y2 = fmaxf(fmaf(a.z - m2, sc2, bt.z), 0.0f);
    float y3 = fmaxf(fmaf(a.w - m3, sc3, bt.w), 0.0f);

    float ss = y0 * y0 + y1 * y1 + y2 * y2 + y3 * y3;
    #pragma unroll
    for (int o = 8; o > 0; o >>= 1)
        ss += __shfl_xor_sync(0xffffffffu, ss, o);   // xor<16 stays in half-warp
    float inv = 1.0f / fmaxf(sqrtf(ss), L2_EPS);
    *(float4*)&out[base + c4] = make_float4(y0 * inv, y1 * inv, y2 * inv, y3 * inv);
}

extern "C" void kernel_launch(void* const* d_in, const int* in_sizes, int n_in,
                              void* d_out, int out_size) {
    const float* x     = (const float*)d_in[0];
    const void*  ei    = d_in[1];                 // int32 or int64, probed on device
    const float* W     = (const float*)d_in[2];
    // const float* b  = (const float*)d_in[3];   // cancels exactly in BN
    const float* gamma = (const float*)d_in[4];
    const float* beta  = (const float*)d_in[5];
    float* out = (float*)d_out;

    int n = in_sizes[0] / DIMK;       // 50000
    int E = in_sizes[1] / 2;          // 800000
    int nblk = (n + SCAN_B - 1) / SCAN_B;   // 49
    int ehalf = (E + 1) / 2;

    static int s_inited = 0;
    static cudaStream_t s_side;
    static cudaEvent_t  s_fork, s_join;
    if (!s_inited) {
        cudaStreamCreateWithFlags(&s_side, cudaStreamNonBlocking);
        cudaEventCreateWithFlags(&s_fork, cudaEventDisableTiming);
        cudaEventCreateWithFlags(&s_join, cudaEventDisableTiming);
        s_inited = 1;
    }

    // Fork: gemm (x,W -> g_hh) runs concurrently with the CSR build.
    cudaEventRecord(s_fork, 0);
    cudaStreamWaitEvent(s_side, s_fork, 0);
    k_gemm<<<(n + 63) / 64, 256, 0, s_side>>>(x, W, n);
    cudaEventRecord(s_join, s_side);

    // Main stream: CSR build (3 launches).
    k_deg <<<(ehalf + 255) / 256, 256>>>(ei, E);
    k_scan<<<nblk, SCAN_B>>>(n, E);
    k_fill<<<(ehalf + 255) / 256, 256>>>(ei, E);

    // Join, then aggregate + finalize.
    cudaStreamWaitEvent(0, s_join, 0);
    k_agg  <<<(n + 7) / 8, 256>>>(n);
    k_final<<<(n * 16 + 255) / 256, 256>>>(gamma, beta, out, n);
}